// round 9
// baseline (speedup 1.0000x reference)
#include <cuda_runtime.h>
#include <cuda_bf16.h>
#include <cuda_fp16.h>
#include <math.h>
#include <stdint.h>

// ---------------------------------------------------------------------------
// TeleChat2 attention block, R8.
// Same numerics as R7 (fp16 1-pass GEMMs, Q hi/lo QK^T, f16x2 exp, 1-pass PV).
// Structural: GEMM 4-stage cp.async pipeline; attention K/V double-buffer
// with one-tile prefetch.
// ---------------------------------------------------------------------------

static constexpr int Bb  = 2;
static constexpr int Ss  = 2048;
static constexpr int HID = 4096;
static constexpr int NH  = 32;
static constexpr int NKV = 8;
static constexpr int HD  = 128;
static constexpr int M_TOK = Bb * Ss;
static constexpr int KVW   = 2 * NKV * HD;

// fp32 scratch (projection outputs)
__device__ float g_Q [(size_t)M_TOK * HID];
__device__ float g_KV[(size_t)M_TOK * KVW];

// fp16 operands
__device__ __half g_hidF [(size_t)M_TOK * HID];
__device__ __half g_WqF  [(size_t)HID * HID];
__device__ __half g_WkvF [(size_t)KVW * HID];
__device__ __half g_WdF  [(size_t)HID * HID];
__device__ __half g_atF  [(size_t)M_TOK * HID];

// fp16 attention operands (head-major)
__device__ __half g_qh[(size_t)M_TOK * HID];
__device__ __half g_ql[(size_t)M_TOK * HID];
__device__ __half g_kF[(size_t)Bb * NKV * Ss * HD];
__device__ __half g_vF[(size_t)Bb * NKV * Ss * HD];

// ---------------------------------------------------------------------------
// helpers
// ---------------------------------------------------------------------------
__device__ __forceinline__ uint32_t smem_u32(const void* p) {
    uint32_t a;
    asm("{ .reg .u64 t; cvta.to.shared.u64 t, %1; cvt.u32.u64 %0, t; }"
        : "=r"(a) : "l"(p));
    return a;
}
__device__ __forceinline__ uint32_t sw_off(int row, int chunk) {
    int unit = ((row & 1) * 4 + chunk) ^ ((row >> 1) & 7);
    return (uint32_t)((row >> 1) * 128 + unit * 16);
}
__device__ __forceinline__ uint32_t sw256(int row, int chunk) {
    return (uint32_t)(row * 256 + (((chunk ^ row) & 7) | (chunk & 8)) * 16);
}

#define LDSM_X4(r, addr) \
    asm volatile("ldmatrix.sync.aligned.m8n8.x4.shared.b16 {%0,%1,%2,%3}, [%4];" \
        : "=r"((r)[0]), "=r"((r)[1]), "=r"((r)[2]), "=r"((r)[3]) : "r"(addr))
#define LDSM_X4_T(r, addr) \
    asm volatile("ldmatrix.sync.aligned.m8n8.x4.trans.shared.b16 {%0,%1,%2,%3}, [%4];" \
        : "=r"((r)[0]), "=r"((r)[1]), "=r"((r)[2]), "=r"((r)[3]) : "r"(addr))

#define MMA_FP16(c, a, b0v, b1v) \
    asm volatile("mma.sync.aligned.m16n8k16.row.col.f32.f16.f16.f32 " \
        "{%0,%1,%2,%3}, {%4,%5,%6,%7}, {%8,%9}, {%0,%1,%2,%3};" \
        : "+f"((c)[0]), "+f"((c)[1]), "+f"((c)[2]), "+f"((c)[3]) \
        : "r"((a)[0]), "r"((a)[1]), "r"((a)[2]), "r"((a)[3]), "r"(b0v), "r"(b1v))

#define CP_ASYNC16(saddr, gptr) \
    asm volatile("cp.async.cg.shared.global [%0], [%1], 16;" \
        :: "r"(saddr), "l"(gptr) : "memory")
#define CP_COMMIT() asm volatile("cp.async.commit_group;" ::: "memory")
#define CP_WAIT(n)  asm volatile("cp.async.wait_group %0;" :: "n"(n) : "memory")

#define EX2_F16X2(d, s) \
    asm("ex2.approx.f16x2 %0, %1;" : "=r"(d) : "r"(s))
#define EX2_F32(d, s) \
    asm("ex2.approx.f32 %0, %1;" : "=f"(d) : "f"(s))

__device__ __forceinline__ void hsplit2(float x, float y,
                                        uint32_t& hi, uint32_t& lo) {
    __half hx = __float2half_rn(x);
    __half hy = __float2half_rn(y);
    __half lx = __float2half_rn(x - __half2float(hx));
    __half ly = __float2half_rn(y - __half2float(hy));
    __half2 h2(hx, hy), l2(lx, ly);
    hi = *(uint32_t*)&h2; lo = *(uint32_t*)&l2;
}

// ---------------------------------------------------------------------------
// fp32 -> fp16 (activations)
// ---------------------------------------------------------------------------
__global__ __launch_bounds__(256) void conv_fp16_kernel(
    const float* __restrict__ in, __half* __restrict__ out, int n4)
{
    int i = blockIdx.x * blockDim.x + threadIdx.x;
    int stride = gridDim.x * blockDim.x;
    const float4* in4 = (const float4*)in;
    __half2* o2 = (__half2*)out;
    for (; i < n4; i += stride) {
        float4 v = in4[i];
        o2[2 * i]     = __floats2half2_rn(v.x, v.y);
        o2[2 * i + 1] = __floats2half2_rn(v.z, v.w);
    }
}

// ---------------------------------------------------------------------------
// fp32 weights -> fp16 of 32*W (single rounding)
// ---------------------------------------------------------------------------
__global__ __launch_bounds__(256) void conv_wscale_kernel(
    const float* __restrict__ in, __half* __restrict__ out, int n4)
{
    int i = blockIdx.x * blockDim.x + threadIdx.x;
    int stride = gridDim.x * blockDim.x;
    const float4* in4 = (const float4*)in;
    __half2* o2 = (__half2*)out;
    for (; i < n4; i += stride) {
        float4 v = in4[i];
        o2[2 * i]     = __floats2half2_rn(v.x * 32.0f, v.y * 32.0f);
        o2[2 * i + 1] = __floats2half2_rn(v.z * 32.0f, v.w * 32.0f);
    }
}

// ---------------------------------------------------------------------------
// Tensor-core GEMM, fp16 1-pass, 4-stage cp.async pipeline.
// C[m,n] = (1/32) * sum_k A[m,k]*W[n,k] (+bias).
// CTA 128x128, BK=32, 256 threads = 8 warps (2m x 4n). 16KB/stage x 4.
// ---------------------------------------------------------------------------
static constexpr int GT = 8192;
static constexpr int GSTAGE = 2 * GT;            // 16 KB
static constexpr int GEMM_SMEM = 4 * GSTAGE;     // 64 KB

__global__ __launch_bounds__(256) void gemm_fp16_kernel(
    const __half* __restrict__ A, const __half* __restrict__ B,
    const float* __restrict__ bias, float* __restrict__ C,
    int M, int N, int K)
{
    extern __shared__ char smem[];
    const uint32_t sb = smem_u32(smem);
    const int tid  = threadIdx.x;
    const int wid  = tid >> 5;
    const int lane = tid & 31;
    const int bm = blockIdx.y * 128;
    const int bn = blockIdx.x * 128;
    const int m0 = (wid >> 2) * 64;
    const int n0 = (wid & 3) * 32;

    float acc[4][4][4];
#pragma unroll
    for (int i = 0; i < 4; i++)
#pragma unroll
        for (int j = 0; j < 4; j++)
#pragma unroll
            for (int r = 0; r < 4; r++) acc[i][j][r] = 0.0f;

    const int nchunk = K >> 5;   // 128 for K=4096

    auto load_stage = [&](int c, int stage) {
        const int k0 = c << 5;
        const uint32_t sbase = sb + stage * GSTAGE;
#pragma unroll
        for (int t = 0; t < 4; t++) {
            int op   = tid + t * 256;      // 0..1023
            int tile = op >> 9;            // 0 A, 1 B
            int idx  = op & 511;
            int row  = idx >> 2;
            int ch   = idx & 3;
            const __half* src = (tile == 0) ? A : B;
            int grow = ((tile == 0) ? bm : bn) + row;
            const void* g = src + (size_t)grow * K + k0 + ch * 8;
            uint32_t saddr = sbase + (uint32_t)tile * GT + sw_off(row, ch);
            CP_ASYNC16(saddr, g);
        }
        CP_COMMIT();
    };

    const int rA = ((lane >> 3) & 1) * 8 + (lane & 7);
    const int cA = (lane >> 4);
    const int rB = ((lane >> 4) & 1) * 8 + (lane & 7);
    const int cB = ((lane >> 3) & 1);

    // prologue: fill 3 stages
    load_stage(0, 0);
    load_stage(1, 1);
    load_stage(2, 2);

    for (int c = 0; c < nchunk; c++) {
        if (c + 3 < nchunk) {
            // stage (c+3)&3 == (c-1)&3: its consumers finished at the barrier
            // that ended iteration c-1.
            load_stage(c + 3, (c + 3) & 3);
            CP_WAIT(3);                     // 4 pending -> chunk c landed
        } else {
            CP_WAIT(0);
        }
        __syncthreads();

        const uint32_t sbase = sb + (c & 3) * GSTAGE;
#pragma unroll
        for (int s = 0; s < 2; s++) {
            uint32_t af[4][4], bf[2][4];
#pragma unroll
            for (int i = 0; i < 4; i++) {
                uint32_t off = sw_off(m0 + i * 16 + rA, 2 * s + cA);
                LDSM_X4(af[i], sbase + off);
            }
#pragma unroll
            for (int j2 = 0; j2 < 2; j2++) {
                uint32_t off = sw_off(n0 + j2 * 16 + rB, 2 * s + cB);
                LDSM_X4(bf[j2], sbase + GT + off);
            }
#pragma unroll
            for (int i = 0; i < 4; i++)
#pragma unroll
                for (int j2 = 0; j2 < 2; j2++)
#pragma unroll
                    for (int jj = 0; jj < 2; jj++) {
                        float* cc = acc[i][j2 * 2 + jj];
                        MMA_FP16(cc, af[i], bf[j2][jj * 2], bf[j2][jj * 2 + 1]);
                    }
        }
        __syncthreads();
    }

    const float inv32 = 0.03125f;
#pragma unroll
    for (int i = 0; i < 4; i++) {
#pragma unroll
        for (int j = 0; j < 4; j++) {
            int row = bm + m0 + i * 16 + (lane >> 2);
            int col = bn + n0 + j * 8 + (lane & 3) * 2;
            float bx = 0.0f, by = 0.0f;
            if (bias) { bx = bias[col]; by = bias[col + 1]; }
            float2 v0 = make_float2(acc[i][j][0] * inv32 + bx,
                                    acc[i][j][1] * inv32 + by);
            float2 v1 = make_float2(acc[i][j][2] * inv32 + bx,
                                    acc[i][j][3] * inv32 + by);
            *(float2*)(C + (size_t)row * N + col) = v0;
            *(float2*)(C + (size_t)(row + 8) * N + col) = v1;
        }
    }
}

// ---------------------------------------------------------------------------
// RoPE on Q -> fp16 hi/lo (UNSCALED), head-major [b,h,s,d].
// ---------------------------------------------------------------------------
__global__ __launch_bounds__(256) void rope_q_split_kernel(
    const float* __restrict__ Q, const float* __restrict__ cosT,
    const float* __restrict__ sinT, __half* __restrict__ qh,
    __half* __restrict__ ql)
{
    const int row = blockIdx.x;
    const int b = row >> 11;
    const int s = row & (Ss - 1);
    const float* qrow = Q + (size_t)row * HID;
    const float* cr = cosT + (size_t)s * HD;
    const float* sr = sinT + (size_t)s * HD;
    for (int p = threadIdx.x; p < NH * 32; p += blockDim.x) {
        const int h = p >> 5;
        const int d = (p & 31) * 2;
        const float* q = qrow + h * HD;
        float lo0 = q[d],      lo1 = q[d + 1];
        float hi0 = q[d + 64], hi1 = q[d + 65];
        float e0 = lo0 * cr[d]     - hi0 * sr[d];
        float e1 = lo1 * cr[d + 1] - hi1 * sr[d + 1];
        float f0 = hi0 * cr[d + 64] + lo0 * sr[d + 64];
        float f1 = hi1 * cr[d + 65] + lo1 * sr[d + 65];
        size_t ob = ((size_t)(b * NH + h) * Ss + s) * HD;
        uint32_t ph, pl;
        hsplit2(e0, e1, ph, pl);
        *(uint32_t*)(qh + ob + d) = ph; *(uint32_t*)(ql + ob + d) = pl;
        hsplit2(f0, f1, ph, pl);
        *(uint32_t*)(qh + ob + d + 64) = ph; *(uint32_t*)(ql + ob + d + 64) = pl;
    }
}

// ---------------------------------------------------------------------------
// RoPE on K + V copy -> single fp16, head-major [b,kv,s,d].
// ---------------------------------------------------------------------------
__global__ __launch_bounds__(256) void rope_kv_split_kernel(
    const float* __restrict__ KV, const float* __restrict__ cosT,
    const float* __restrict__ sinT,
    __half* __restrict__ kF, __half* __restrict__ vF)
{
    const int row = blockIdx.x;
    const int b = row >> 11;
    const int s = row & (Ss - 1);
    const float* kvrow = KV + (size_t)row * KVW;
    const float* cr = cosT + (size_t)s * HD;
    const float* sr = sinT + (size_t)s * HD;
    for (int p = threadIdx.x; p < NKV * 32; p += blockDim.x) {
        const int kv = p >> 5;
        const int d = (p & 31) * 2;
        const float* k = kvrow + kv * (2 * HD);
        const float* v = k + HD;
        float lo0 = k[d],      lo1 = k[d + 1];
        float hi0 = k[d + 64], hi1 = k[d + 65];
        float e0 = lo0 * cr[d]     - hi0 * sr[d];
        float e1 = lo1 * cr[d + 1] - hi1 * sr[d + 1];
        float f0 = hi0 * cr[d + 64] + lo0 * sr[d + 64];
        float f1 = hi1 * cr[d + 65] + lo1 * sr[d + 65];
        size_t ob = ((size_t)(b * NKV + kv) * Ss + s) * HD;
        *(__half2*)(kF + ob + d)      = __floats2half2_rn(e0, e1);
        *(__half2*)(kF + ob + d + 64) = __floats2half2_rn(f0, f1);
        *(__half2*)(vF + ob + d)      = __floats2half2_rn(v[d], v[d + 1]);
        *(__half2*)(vF + ob + d + 64) = __floats2half2_rn(v[d + 64], v[d + 65]);
    }
}

// ---------------------------------------------------------------------------
// Flash attention with K/V double-buffer prefetch.
// Grid (S/64, NH, B), 128 threads (4 warps).
// smem: Qh, Ql, K0, V0, K1, V1 (16KB each) = 96KB -> 2 CTAs/SM.
// QK^T fp16 2-pass; softmax via ex2.approx.f16x2 (log2 domain); PV 1-pass.
// ---------------------------------------------------------------------------
static constexpr int AT = 64 * 256;
static constexpr int ATTN_SMEM = 6 * AT;   // 96 KB

__global__ __launch_bounds__(128) void flash_attn_mma_kernel(
    const __half* __restrict__ qh, const __half* __restrict__ ql,
    const __half* __restrict__ kF, const __half* __restrict__ vF,
    __half* __restrict__ atF)
{
    extern __shared__ char smem[];
    const uint32_t sb = smem_u32(smem);
    const int qt = blockIdx.x;
    const int h  = blockIdx.y;
    const int b  = blockIdx.z;
    const int kvh = h >> 2;
    const int tid = threadIdx.x;
    const int wid = tid >> 5;
    const int lane = tid & 31;
    const int r0 = wid * 16;
    const float kscale = 0.1275187952462235f;  // (1/sqrt(128)) * log2(e)

    const int rA = (lane & 7) + ((lane >> 3) & 1) * 8;
    const int cA = lane >> 4;
    const int rB = (lane & 7) + ((lane >> 4) & 1) * 8;
    const int cB = (lane >> 3) & 1;

    const size_t kvbase = ((size_t)(b * NKV + kvh) * Ss) * HD;

    auto load_kv = [&](int kt, int buf) {
        const size_t kb = kvbase + (size_t)kt * 64 * HD;
        const uint32_t kdst = sb + (2 + 2 * buf) * AT;
        for (int idx = tid; idx < 1024; idx += 128) {
            int r = idx >> 4, ch = idx & 15;
            uint32_t so = sw256(r, ch);
            const size_t g = kb + (size_t)r * HD + ch * 8;
            CP_ASYNC16(kdst + so, kF + g);
            CP_ASYNC16(kdst + AT + so, vF + g);
        }
        CP_COMMIT();
    };

    // group 0: Q tiles; group 1: K/V for kt=0
    const size_t qbase = ((size_t)(b * NH + h) * Ss + (size_t)qt * 64) * HD;
    for (int idx = tid; idx < 1024; idx += 128) {
        int r = idx >> 4, ch = idx & 15;
        uint32_t so = sw256(r, ch);
        const size_t g = qbase + (size_t)r * HD + ch * 8;
        CP_ASYNC16(sb + so, qh + g);
        CP_ASYNC16(sb + AT + so, ql + g);
    }
    CP_COMMIT();
    load_kv(0, 0);

    float oacc[16][4];
#pragma unroll
    for (int i = 0; i < 16; i++)
#pragma unroll
        for (int j = 0; j < 4; j++) oacc[i][j] = 0.0f;
    float mrow[2] = {-1e30f, -1e30f};
    float lrow[2] = {0.0f, 0.0f};

    for (int kt = 0; kt <= qt; kt++) {
        // prefetch next K/V tile; its buffer was consumed at kt-1 and is
        // protected by the barrier that ended the previous iteration.
        if (kt < qt) { load_kv(kt + 1, (kt + 1) & 1); CP_WAIT(1); }
        else         { CP_WAIT(0); }
        __syncthreads();

        const uint32_t ksb = sb + (2 + 2 * (kt & 1)) * AT;   // K tile
        const uint32_t vsb = ksb + AT;                        // V tile

        // ---- S = Q K^T (2-pass: Qh + Ql vs single K) ----
        float sacc[8][4];
#pragma unroll
        for (int i = 0; i < 8; i++)
#pragma unroll
            for (int j = 0; j < 4; j++) sacc[i][j] = 0.0f;

#pragma unroll
        for (int kc = 0; kc < 8; kc++) {
            uint32_t ah[4], al[4];
            uint32_t offA = sw256(r0 + rA, 2 * kc + cA);
            LDSM_X4(ah, sb + offA);
            LDSM_X4(al, sb + AT + offA);
#pragma unroll
            for (int nbp = 0; nbp < 4; nbp++) {
                uint32_t bk[4];
                uint32_t offB = sw256(nbp * 16 + rB, 2 * kc + cB);
                LDSM_X4(bk, ksb + offB);
#pragma unroll
                for (int jj = 0; jj < 2; jj++) {
                    float* cc = sacc[nbp * 2 + jj];
                    MMA_FP16(cc, ah, bk[jj * 2], bk[jj * 2 + 1]);
                    MMA_FP16(cc, al, bk[jj * 2], bk[jj * 2 + 1]);
                }
            }
        }

        // scale into log2 domain
#pragma unroll
        for (int nb = 0; nb < 8; nb++) {
#pragma unroll
            for (int j = 0; j < 4; j++) sacc[nb][j] *= kscale;
        }

        // ---- causal mask on diagonal tile ----
        if (kt == qt) {
            const int rl = lane >> 2;
            const int c0 = (lane & 3) * 2;
#pragma unroll
            for (int nb = 0; nb < 8; nb++) {
#pragma unroll
                for (int j = 0; j < 4; j++) {
                    int col = nb * 8 + c0 + (j & 1);
                    int row = r0 + rl + (j >> 1) * 8;
                    if (col > row) sacc[nb][j] = -1e30f;
                }
            }
        }

        // ---- online softmax (log2 domain, 2 rows per lane) ----
        float mx0 = -1e30f, mx1 = -1e30f;
#pragma unroll
        for (int nb = 0; nb < 8; nb++) {
            mx0 = fmaxf(mx0, fmaxf(sacc[nb][0], sacc[nb][1]));
            mx1 = fmaxf(mx1, fmaxf(sacc[nb][2], sacc[nb][3]));
        }
        mx0 = fmaxf(mx0, __shfl_xor_sync(0xffffffffu, mx0, 1));
        mx0 = fmaxf(mx0, __shfl_xor_sync(0xffffffffu, mx0, 2));
        mx1 = fmaxf(mx1, __shfl_xor_sync(0xffffffffu, mx1, 1));
        mx1 = fmaxf(mx1, __shfl_xor_sync(0xffffffffu, mx1, 2));
        float mn0 = fmaxf(mrow[0], mx0);
        float mn1 = fmaxf(mrow[1], mx1);
        float fac0, fac1;
        EX2_F32(fac0, mrow[0] - mn0);
        EX2_F32(fac1, mrow[1] - mn1);
        mrow[0] = mn0; mrow[1] = mn1;
        lrow[0] *= fac0; lrow[1] *= fac1;

        uint32_t aP[4][4];
        uint32_t lh0 = 0, lh1 = 0;
#pragma unroll
        for (int nb = 0; nb < 8; nb++) {
            __half2 h01 = __floats2half2_rn(sacc[nb][0] - mn0, sacc[nb][1] - mn0);
            __half2 h23 = __floats2half2_rn(sacc[nb][2] - mn1, sacc[nb][3] - mn1);
            uint32_t p01, p23;
            EX2_F16X2(p01, *(uint32_t*)&h01);
            EX2_F16X2(p23, *(uint32_t*)&h23);
            const int kc2 = nb >> 1;
            aP[kc2][(nb & 1) * 2 + 0] = p01;
            aP[kc2][(nb & 1) * 2 + 1] = p23;
            __half2 s0 = __hadd2(*(__half2*)&lh0, *(__half2*)&p01);
            __half2 s1 = __hadd2(*(__half2*)&lh1, *(__half2*)&p23);
            lh0 = *(uint32_t*)&s0; lh1 = *(uint32_t*)&s1;
        }
        {
            __half2 L0 = *(__half2*)&lh0;
            __half2 L1 = *(__half2*)&lh1;
            lrow[0] += __low2float(L0) + __high2float(L0);
            lrow[1] += __low2float(L1) + __high2float(L1);
        }
#pragma unroll
        for (int db = 0; db < 16; db++) {
            oacc[db][0] *= fac0; oacc[db][1] *= fac0;
            oacc[db][2] *= fac1; oacc[db][3] *= fac1;
        }

        // ---- O += P V (1-pass) ----
#pragma unroll
        for (int kc2 = 0; kc2 < 4; kc2++) {
#pragma unroll
            for (int dbp = 0; dbp < 8; dbp++) {
                uint32_t vf[4];
                uint32_t offV = sw256(kc2 * 16 + rA, 2 * dbp + cA);
                LDSM_X4_T(vf, vsb + offV);
#pragma unroll
                for (int jj = 0; jj < 2; jj++) {
                    float* cc = oacc[dbp * 2 + jj];
                    MMA_FP16(cc, aP[kc2], vf[jj * 2], vf[jj * 2 + 1]);
                }
            }
        }
        __syncthreads();   // next iteration overwrites this kt's buffer pair
    }

    // ---- finalize ----
    lrow[0] += __shfl_xor_sync(0xffffffffu, lrow[0], 1);
    lrow[0] += __shfl_xor_sync(0xffffffffu, lrow[0], 2);
    lrow[1] += __shfl_xor_sync(0xffffffffu, lrow[1], 1);
    lrow[1] += __shfl_xor_sync(0xffffffffu, lrow[1], 2);
    const float inv0 = 1.0f / lrow[0];
    const float inv1 = 1.0f / lrow[1];
    const int rl = lane >> 2;
    const int c0 = (lane & 3) * 2;
    const size_t row0 = (size_t)(b * Ss + qt * 64 + r0 + rl) * HID + h * HD;
    const size_t row1 = row0 + (size_t)8 * HID;
#pragma unroll
    for (int db = 0; db < 16; db++) {
        const int col = db * 8 + c0;
        __half2 a = __floats2half2_rn(oacc[db][0] * inv0, oacc[db][1] * inv0);
        __half2 c = __floats2half2_rn(oacc[db][2] * inv1, oacc[db][3] * inv1);
        *(__half2*)(atF + row0 + col) = a;
        *(__half2*)(atF + row1 + col) = c;
    }
}

// ---------------------------------------------------------------------------
// Launch
// ---------------------------------------------------------------------------
extern "C" void kernel_launch(void* const* d_in, const int* in_sizes, int n_in,
                              void* d_out, int out_size)
{
    const float* hidden = (const float*)d_in[0];
    const float* cosT = (const float*)d_in[2];
    const float* sinT = (const float*)d_in[3];
    const float* Wq   = (const float*)d_in[4];
    const float* Wkv  = (const float*)d_in[5];
    const float* Wd   = (const float*)d_in[6];
    const float* bd   = (const float*)d_in[7];
    float* out = (float*)d_out;

    float *Qb, *KVb;
    cudaGetSymbolAddress((void**)&Qb,  g_Q);
    cudaGetSymbolAddress((void**)&KVb, g_KV);

    __half *hidF, *wqF, *wkvF, *wdF, *atF;
    cudaGetSymbolAddress((void**)&hidF, g_hidF);
    cudaGetSymbolAddress((void**)&wqF,  g_WqF);
    cudaGetSymbolAddress((void**)&wkvF, g_WkvF);
    cudaGetSymbolAddress((void**)&wdF,  g_WdF);
    cudaGetSymbolAddress((void**)&atF,  g_atF);

    __half *qh, *ql, *kF, *vF;
    cudaGetSymbolAddress((void**)&qh, g_qh);
    cudaGetSymbolAddress((void**)&ql, g_ql);
    cudaGetSymbolAddress((void**)&kF, g_kF);
    cudaGetSymbolAddress((void**)&vF, g_vF);

    cudaFuncSetAttribute(gemm_fp16_kernel,
                         cudaFuncAttributeMaxDynamicSharedMemorySize, GEMM_SMEM);
    cudaFuncSetAttribute(flash_attn_mma_kernel,
                         cudaFuncAttributeMaxDynamicSharedMemorySize, ATTN_SMEM);

    const int n_hid = M_TOK * HID / 4;
    const int n_wkv = KVW * HID / 4;
    conv_fp16_kernel  <<<2048, 256>>>(hidden, hidF, n_hid);
    conv_wscale_kernel<<<2048, 256>>>(Wq,  wqF,  n_hid);
    conv_wscale_kernel<<<2048, 256>>>(Wkv, wkvF, n_wkv);
    conv_wscale_kernel<<<2048, 256>>>(Wd,  wdF,  n_hid);

    gemm_fp16_kernel<<<dim3(HID / 128, M_TOK / 128), 256, GEMM_SMEM>>>(
        hidF, wqF, nullptr, Qb, M_TOK, HID, HID);
    gemm_fp16_kernel<<<dim3(KVW / 128, M_TOK / 128), 256, GEMM_SMEM>>>(
        hidF, wkvF, nullptr, KVb, M_TOK, KVW, HID);

    rope_q_split_kernel<<<M_TOK, 256>>>(Qb, cosT, sinT, qh, ql);
    rope_kv_split_kernel<<<M_TOK, 256>>>(KVb, cosT, sinT, kF, vF);

    flash_attn_mma_kernel<<<dim3(Ss / 64, NH, Bb), 128, ATTN_SMEM>>>(
        qh, ql, kF, vF, atF);

    gemm_fp16_kernel<<<dim3(HID / 128, M_TOK / 128), 256, GEMM_SMEM>>>(
        atF, wdF, bd, out, M_TOK, HID, HID);
}